// round 1
// baseline (speedup 1.0000x reference)
#include <cuda_runtime.h>
#include <math_constants.h>

// Problem constants
#define BATCH 4
#define SEQ   2048
#define DMODEL 1024
#define NHEADS 16
#define DHEAD 64
#define NEG_VAL (-32767.0f)     // matches reference mask constant (-2^15 + 1)

// Scratch: qkv projection (B,N,3D) and attention output (B,N,D)
__device__ float g_qkv[(size_t)BATCH * SEQ * 3 * DMODEL];   // 96 MB
__device__ float g_attn[(size_t)BATCH * SEQ * DMODEL];      // 32 MB

// ---------------------------------------------------------------------------
// GEMM: C[M,N] = A[M,K] @ W[N,K]^T + bias[N]
// CONCAT=true: A is the virtual concat [A0|A1|A2] along K (each segment 1024 wide)
// Tiles: BM=BN=128, BK=16, 256 threads, 8x8 per thread (split 4+4 pattern for
// conflict-free LDS.128 of smem fragments).
// ---------------------------------------------------------------------------
template <bool CONCAT>
__global__ void __launch_bounds__(256) gemm_kernel(
    const float* __restrict__ A0, const float* __restrict__ A1,
    const float* __restrict__ A2,
    const float* __restrict__ W, const float* __restrict__ bias,
    float* __restrict__ C, int M, int N, int K)
{
    __shared__ float As[16][132];
    __shared__ float Bs[16][132];

    const int tid = threadIdx.x;
    const int ry = tid >> 4;        // 0..15
    const int tx = tid & 15;        // 0..15
    const int m0 = blockIdx.y * 128;
    const int n0 = blockIdx.x * 128;

    float acc[8][8];
#pragma unroll
    for (int i = 0; i < 8; i++)
#pragma unroll
        for (int j = 0; j < 8; j++) acc[i][j] = 0.f;

    const int nkt = K >> 4;
    for (int kt = 0; kt < nkt; kt++) {
        const int k0 = kt << 4;
        const float* Abase;
        int ldA, kin;
        if (CONCAT) {
            const int seg = k0 >> 10;                 // 16-wide tile never crosses a 1024 boundary
            Abase = (seg == 0) ? A0 : ((seg == 1) ? A1 : A2);
            kin = k0 & 1023;
            ldA = 1024;
        } else {
            Abase = A0; kin = k0; ldA = K;
        }
#pragma unroll
        for (int t = 0; t < 2; t++) {
            const int idx = tid + t * 256;            // 0..511
            const int row = idx >> 2;                 // 0..127
            const int c4  = (idx & 3) << 2;           // 0,4,8,12
            float4 va = *(const float4*)(Abase + (size_t)(m0 + row) * ldA + kin + c4);
            As[c4 + 0][row] = va.x; As[c4 + 1][row] = va.y;
            As[c4 + 2][row] = va.z; As[c4 + 3][row] = va.w;
            float4 vw = *(const float4*)(W + (size_t)(n0 + row) * K + k0 + c4);
            Bs[c4 + 0][row] = vw.x; Bs[c4 + 1][row] = vw.y;
            Bs[c4 + 2][row] = vw.z; Bs[c4 + 3][row] = vw.w;
        }
        __syncthreads();

#pragma unroll
        for (int kk = 0; kk < 16; kk++) {
            float a[8], b[8];
            *(float4*)&a[0] = *(const float4*)&As[kk][ry * 4];
            *(float4*)&a[4] = *(const float4*)&As[kk][64 + ry * 4];
            *(float4*)&b[0] = *(const float4*)&Bs[kk][tx * 4];
            *(float4*)&b[4] = *(const float4*)&Bs[kk][64 + tx * 4];
#pragma unroll
            for (int i = 0; i < 8; i++)
#pragma unroll
                for (int j = 0; j < 8; j++)
                    acc[i][j] = fmaf(a[i], b[j], acc[i][j]);
        }
        __syncthreads();
    }

    // epilogue: bias + store (float4)
#pragma unroll
    for (int i = 0; i < 8; i++) {
        const int r = m0 + ((i < 4) ? (ry * 4 + i) : (64 + ry * 4 + (i - 4)));
#pragma unroll
        for (int jh = 0; jh < 2; jh++) {
            const int c = n0 + (jh ? (64 + tx * 4) : (tx * 4));
            float4 o;
            o.x = acc[i][jh * 4 + 0] + bias[c + 0];
            o.y = acc[i][jh * 4 + 1] + bias[c + 1];
            o.z = acc[i][jh * 4 + 2] + bias[c + 2];
            o.w = acc[i][jh * 4 + 3] + bias[c + 3];
            *(float4*)(C + (size_t)r * N + c) = o;
        }
    }
}

// ---------------------------------------------------------------------------
// Causal flash attention, fp32. One CTA = (b, h, 64-row tile).
// 64x64 K/V tiles streamed; online softmax; P overwrites K's smem buffer.
// smem: Qs[64][68] + Ks[64][68] + Vs[64][64] = 51200 B (dynamic).
// Thread layout 16x16, each owning a 4x4 of S / O.
// ---------------------------------------------------------------------------
__global__ void __launch_bounds__(256) attn_kernel(
    const float* __restrict__ qkv, float* __restrict__ outp)
{
    extern __shared__ float sm[];
    float* Qs = sm;                    // stride 68
    float* Ks = sm + 64 * 68;          // stride 68 (reused as P after S compute)
    float* Vs = sm + 2 * 64 * 68;      // stride 64

    const int tid = threadIdx.x;
    const int ty = tid >> 4;           // 0..15
    const int tx = tid & 15;           // 0..15
    const int r0 = ty * 4;
    const int c0 = tx * 4;

    const int rt = blockIdx.x;         // row tile (0..31)
    const int h  = blockIdx.y;         // head
    const int b  = blockIdx.z;         // batch
    const int g0 = rt * 64;

    const size_t rowbase = (size_t)b * SEQ * (3 * DMODEL);
    const int qcol = h * DHEAD;
    const int kcol = DMODEL + h * DHEAD;
    const int vcol = 2 * DMODEL + h * DHEAD;

    // Load Q tile (64 rows x 64 cols)
#pragma unroll
    for (int t = 0; t < 4; t++) {
        const int idx = tid + t * 256;
        const int row = idx >> 4;
        const int cc  = (idx & 15) << 2;
        *(float4*)&Qs[row * 68 + cc] =
            *(const float4*)(qkv + rowbase + (size_t)(g0 + row) * (3 * DMODEL) + qcol + cc);
    }

    float m[4], l[4], o[4][4];
#pragma unroll
    for (int i = 0; i < 4; i++) {
        m[i] = -CUDART_INF_F; l[i] = 0.f;
#pragma unroll
        for (int j = 0; j < 4; j++) o[i][j] = 0.f;
    }

    for (int jt = 0; jt <= rt; jt++) {
        const int j0 = jt * 64;
        __syncthreads();   // previous PV reads done before K/V overwrite
#pragma unroll
        for (int t = 0; t < 4; t++) {
            const int idx = tid + t * 256;
            const int row = idx >> 4;
            const int cc  = (idx & 15) << 2;
            const size_t base = rowbase + (size_t)(j0 + row) * (3 * DMODEL);
            *(float4*)&Ks[row * 68 + cc] = *(const float4*)(qkv + base + kcol + cc);
            *(float4*)&Vs[row * 64 + cc] = *(const float4*)(qkv + base + vcol + cc);
        }
        __syncthreads();

        // S = (Q @ K^T) * 8
        float s[4][4];
#pragma unroll
        for (int i = 0; i < 4; i++)
#pragma unroll
            for (int j = 0; j < 4; j++) s[i][j] = 0.f;

#pragma unroll 4
        for (int kk = 0; kk < 64; kk += 4) {
            float4 a[4], bb[4];
#pragma unroll
            for (int i = 0; i < 4; i++) a[i]  = *(const float4*)&Qs[(r0 + i) * 68 + kk];
#pragma unroll
            for (int j = 0; j < 4; j++) bb[j] = *(const float4*)&Ks[(c0 + j) * 68 + kk];
#pragma unroll
            for (int i = 0; i < 4; i++)
#pragma unroll
                for (int j = 0; j < 4; j++) {
                    s[i][j] = fmaf(a[i].x, bb[j].x, s[i][j]);
                    s[i][j] = fmaf(a[i].y, bb[j].y, s[i][j]);
                    s[i][j] = fmaf(a[i].z, bb[j].z, s[i][j]);
                    s[i][j] = fmaf(a[i].w, bb[j].w, s[i][j]);
                }
        }

        const bool diag = (jt == rt);
#pragma unroll
        for (int i = 0; i < 4; i++)
#pragma unroll
            for (int j = 0; j < 4; j++) {
                float v = s[i][j] * 8.0f;   // scale = sqrt(d_head), MULTIPLIED per reference
                if (diag && (j0 + c0 + j > g0 + r0 + i)) v = NEG_VAL;
                s[i][j] = v;
            }

        __syncthreads();   // everyone finished reading Ks before it becomes Ps

        // Online softmax update
        float p[4][4];
#pragma unroll
        for (int i = 0; i < 4; i++) {
            float mx = fmaxf(fmaxf(s[i][0], s[i][1]), fmaxf(s[i][2], s[i][3]));
#pragma unroll
            for (int off = 8; off; off >>= 1)
                mx = fmaxf(mx, __shfl_xor_sync(0xffffffffu, mx, off));
            const float mn = fmaxf(m[i], mx);
            const float al = __expf(m[i] - mn);
            float ps = 0.f;
#pragma unroll
            for (int j = 0; j < 4; j++) {
                const float pv = __expf(s[i][j] - mn);
                p[i][j] = pv; ps += pv;
            }
#pragma unroll
            for (int off = 8; off; off >>= 1)
                ps += __shfl_xor_sync(0xffffffffu, ps, off);
            l[i] = l[i] * al + ps;
            m[i] = mn;
#pragma unroll
            for (int j = 0; j < 4; j++) o[i][j] *= al;
        }

        // P -> smem (reuse Ks buffer)
#pragma unroll
        for (int i = 0; i < 4; i++)
            *(float4*)&Ks[(r0 + i) * 68 + c0] =
                make_float4(p[i][0], p[i][1], p[i][2], p[i][3]);
        __syncthreads();

        // O += P @ V
#pragma unroll 4
        for (int kk = 0; kk < 64; kk += 4) {
            float4 pr[4], vv[4];
#pragma unroll
            for (int i = 0; i < 4; i++) pr[i] = *(const float4*)&Ks[(r0 + i) * 68 + kk];
#pragma unroll
            for (int t = 0; t < 4; t++) vv[t] = *(const float4*)&Vs[(kk + t) * 64 + c0];
#pragma unroll
            for (int i = 0; i < 4; i++) {
                o[i][0] = fmaf(pr[i].x, vv[0].x, o[i][0]);
                o[i][0] = fmaf(pr[i].y, vv[1].x, o[i][0]);
                o[i][0] = fmaf(pr[i].z, vv[2].x, o[i][0]);
                o[i][0] = fmaf(pr[i].w, vv[3].x, o[i][0]);
                o[i][1] = fmaf(pr[i].x, vv[0].y, o[i][1]);
                o[i][1] = fmaf(pr[i].y, vv[1].y, o[i][1]);
                o[i][1] = fmaf(pr[i].z, vv[2].y, o[i][1]);
                o[i][1] = fmaf(pr[i].w, vv[3].y, o[i][1]);
                o[i][2] = fmaf(pr[i].x, vv[0].z, o[i][2]);
                o[i][2] = fmaf(pr[i].y, vv[1].z, o[i][2]);
                o[i][2] = fmaf(pr[i].z, vv[2].z, o[i][2]);
                o[i][2] = fmaf(pr[i].w, vv[3].z, o[i][2]);
                o[i][3] = fmaf(pr[i].x, vv[0].w, o[i][3]);
                o[i][3] = fmaf(pr[i].y, vv[1].w, o[i][3]);
                o[i][3] = fmaf(pr[i].z, vv[2].w, o[i][3]);
                o[i][3] = fmaf(pr[i].w, vv[3].w, o[i][3]);
            }
        }
    }

    // epilogue: O / l -> (B, N, D) layout
#pragma unroll
    for (int i = 0; i < 4; i++) {
        const float inv = 1.0f / l[i];
        const size_t obase = ((size_t)b * SEQ + g0 + r0 + i) * DMODEL + h * DHEAD + c0;
        *(float4*)(outp + obase) =
            make_float4(o[i][0] * inv, o[i][1] * inv, o[i][2] * inv, o[i][3] * inv);
    }
}

// ---------------------------------------------------------------------------
extern "C" void kernel_launch(void* const* d_in, const int* in_sizes, int n_in,
                              void* d_out, int out_size)
{
    const float* q     = (const float*)d_in[0];
    const float* k     = (const float*)d_in[1];
    const float* v     = (const float*)d_in[2];
    const float* w_qkv = (const float*)d_in[3];
    const float* b_qkv = (const float*)d_in[4];
    const float* w_out = (const float*)d_in[5];
    const float* b_out = (const float*)d_in[6];
    float* out = (float*)d_out;

    float *qkvp, *attnp;
    cudaGetSymbolAddress((void**)&qkvp, g_qkv);
    cudaGetSymbolAddress((void**)&attnp, g_attn);

    // 1) QKV projection: (8192 x 3072) = concat(q,k,v) @ w_qkv^T + b_qkv
    dim3 g1(3 * DMODEL / 128, (BATCH * SEQ) / 128);
    gemm_kernel<true><<<g1, 256>>>(q, k, v, w_qkv, b_qkv, qkvp,
                                   BATCH * SEQ, 3 * DMODEL, 3 * DMODEL);

    // 2) Causal flash attention
    cudaFuncSetAttribute(attn_kernel,
                         cudaFuncAttributeMaxDynamicSharedMemorySize, 51200);
    dim3 g2(SEQ / 64, NHEADS, BATCH);
    attn_kernel<<<g2, 256, 51200>>>(qkvp, attnp);

    // 3) Output projection: (8192 x 1024) @ w_out^T + b_out
    dim3 g3(DMODEL / 128, (BATCH * SEQ) / 128);
    gemm_kernel<false><<<g3, 256>>>(attnp, nullptr, nullptr, w_out, b_out, out,
                                    BATCH * SEQ, DMODEL, DMODEL);
}

// round 4
// speedup vs baseline: 1.4844x; 1.4844x over previous
#include <cuda_runtime.h>
#include <cuda_bf16.h>
#include <math_constants.h>
#include <cstdint>

// Problem constants
#define BATCH 4
#define SEQ   2048
#define DMODEL 1024
#define NHEADS 16
#define DHEAD 64
#define NEG_VAL (-32767.0f)

// Scratch
__device__ float g_qkv[(size_t)BATCH * SEQ * 3 * DMODEL];   // 96 MB
__device__ float g_attn[(size_t)BATCH * SEQ * DMODEL];      // 32 MB

// ===========================================================================
// helpers
// ===========================================================================
__device__ __forceinline__ uint32_t smem_u32(const void* p) {
    uint32_t a;
    asm("{ .reg .u64 t; cvta.to.shared.u64 t, %1; cvt.u32.u64 %0, t; }"
        : "=r"(a) : "l"(p));
    return a;
}
__device__ __forceinline__ void ldm_x4(uint32_t* r, uint32_t addr) {
    asm volatile("ldmatrix.sync.aligned.m8n8.x4.shared.b16 {%0,%1,%2,%3}, [%4];"
                 : "=r"(r[0]), "=r"(r[1]), "=r"(r[2]), "=r"(r[3]) : "r"(addr));
}
__device__ __forceinline__ void ldm_x2(uint32_t* r, uint32_t addr) {
    asm volatile("ldmatrix.sync.aligned.m8n8.x2.shared.b16 {%0,%1}, [%2];"
                 : "=r"(r[0]), "=r"(r[1]) : "r"(addr));
}
__device__ __forceinline__ void mma_bf16(float* c, const uint32_t* a, const uint32_t* b) {
    asm volatile(
        "mma.sync.aligned.m16n8k16.row.col.f32.bf16.bf16.f32 "
        "{%0,%1,%2,%3}, {%4,%5,%6,%7}, {%8,%9}, {%0,%1,%2,%3};"
        : "+f"(c[0]), "+f"(c[1]), "+f"(c[2]), "+f"(c[3])
        : "r"(a[0]), "r"(a[1]), "r"(a[2]), "r"(a[3]), "r"(b[0]), "r"(b[1]));
}
__device__ __forceinline__ uint32_t packb(__nv_bfloat16 a, __nv_bfloat16 b) {
    uint16_t ua = *(uint16_t*)&a, ub = *(uint16_t*)&b;
    return (uint32_t)ua | ((uint32_t)ub << 16);
}
// split one float4 into hi/lo bf16x4 packs
__device__ __forceinline__ void split4(float4 v, uint2& hi, uint2& lo) {
    __nv_bfloat16 hx = __float2bfloat16_rn(v.x);
    __nv_bfloat16 hy = __float2bfloat16_rn(v.y);
    __nv_bfloat16 hz = __float2bfloat16_rn(v.z);
    __nv_bfloat16 hw = __float2bfloat16_rn(v.w);
    __nv_bfloat16 lx = __float2bfloat16_rn(v.x - __bfloat162float(hx));
    __nv_bfloat16 ly = __float2bfloat16_rn(v.y - __bfloat162float(hy));
    __nv_bfloat16 lz = __float2bfloat16_rn(v.z - __bfloat162float(hz));
    __nv_bfloat16 lw = __float2bfloat16_rn(v.w - __bfloat162float(hw));
    hi.x = packb(hx, hy); hi.y = packb(hz, hw);
    lo.x = packb(lx, ly); lo.y = packb(lz, lw);
}

// ===========================================================================
// BF16-split mma.sync GEMM: C[M,N] = A[M,K] @ W[N,K]^T + bias[N]
// BM=BN=128, BK=32, 256 threads (2x4 warps, warp tile 64x32),
// double-buffered smem, 3-product error compensation (hi*hi + lo*hi + hi*lo).
// CONCAT: A = [A0|A1|A2] along K (1024-wide segments).
// ===========================================================================
#define BM 128
#define BN 128
#define BK 32
#define RS 40                       // smem row stride in bf16 elements (80B, 16B-aligned)
#define MAT_ELEMS (128 * RS)        // 5120 elements per matrix
#define AHI 0
#define ALO (1 * MAT_ELEMS)
#define BHI (2 * MAT_ELEMS)
#define BLO (3 * MAT_ELEMS)
#define SSTRIDE (4 * MAT_ELEMS)     // 20480 el per stage (40960 B)
#define GEMM_SMEM (2 * SSTRIDE * 2) // bytes: 81920

template <bool CONCAT>
__global__ void __launch_bounds__(256) gemm_mma(
    const float* __restrict__ A0, const float* __restrict__ A1,
    const float* __restrict__ A2,
    const float* __restrict__ W, const float* __restrict__ bias,
    float* __restrict__ C, int M, int N, int K)
{
    extern __shared__ __align__(128) char smraw[];
    __nv_bfloat16* smp = (__nv_bfloat16*)smraw;
    const uint32_t smb = smem_u32(smraw);

    const int tid = threadIdx.x;
    const int lane = tid & 31;
    const int wid = tid >> 5;
    const int wm = wid & 1;            // 0..1
    const int wn = wid >> 1;           // 0..3
    const int m0 = blockIdx.y * BM;
    const int n0 = blockIdx.x * BN;

    float acc[4][4][4];
#pragma unroll
    for (int i = 0; i < 4; i++)
#pragma unroll
        for (int j = 0; j < 4; j++)
#pragma unroll
            for (int e = 0; e < 4; e++) acc[i][j][e] = 0.f;

    const int nkt = K >> 5;
    float4 ra[4], rb[4];

    // ---- prologue: load + split tile 0 ----
    {
        const int k0 = 0;
        const float* Ab; int kin, ldA;
        if (CONCAT) { Ab = A0; kin = 0; ldA = 1024; }
        else        { Ab = A0; kin = 0; ldA = K; }
#pragma unroll
        for (int t = 0; t < 4; t++) {
            const int idx = tid + t * 256;
            const int r = idx >> 3, cb = idx & 7;
            ra[t] = *(const float4*)(Ab + (size_t)(m0 + r) * ldA + kin + cb * 4);
            rb[t] = *(const float4*)(W + (size_t)(n0 + r) * K + k0 + cb * 4);
        }
#pragma unroll
        for (int t = 0; t < 4; t++) {
            const int idx = tid + t * 256;
            const int r = idx >> 3, cb = idx & 7;
            const int off = r * RS + cb * 4;
            uint2 hi, lo;
            split4(ra[t], hi, lo);
            *(uint2*)(smp + AHI + off) = hi;
            *(uint2*)(smp + ALO + off) = lo;
            split4(rb[t], hi, lo);
            *(uint2*)(smp + BHI + off) = hi;
            *(uint2*)(smp + BLO + off) = lo;
        }
    }
    __syncthreads();

    for (int kt = 0; kt < nkt; kt++) {
        const int s = kt & 1;

        // ---- LDG next tile (latency hidden by compute) ----
        if (kt + 1 < nkt) {
            const int k0 = (kt + 1) << 5;
            const float* Ab; int kin, ldA;
            if (CONCAT) {
                const int seg = k0 >> 10;
                Ab = (seg == 0) ? A0 : ((seg == 1) ? A1 : A2);
                kin = k0 & 1023; ldA = 1024;
            } else { Ab = A0; kin = k0; ldA = K; }
#pragma unroll
            for (int t = 0; t < 4; t++) {
                const int idx = tid + t * 256;
                const int r = idx >> 3, cb = idx & 7;
                ra[t] = *(const float4*)(Ab + (size_t)(m0 + r) * ldA + kin + cb * 4);
                rb[t] = *(const float4*)(W + (size_t)(n0 + r) * K + k0 + cb * 4);
            }
        }

        // ---- compute current stage ----
        {
            const uint32_t sb = smb + (uint32_t)s * (SSTRIDE * 2);
#pragma unroll
            for (int ks = 0; ks < 2; ks++) {
                uint32_t bh[4][2], bl[4][2];
#pragma unroll
                for (int nt = 0; nt < 4; nt++) {
                    const int eoff = (wn * 32 + nt * 8 + (lane & 7)) * RS
                                   + ks * 16 + ((lane >> 3) & 1) * 8;
                    ldm_x2(bh[nt], sb + 2u * (BHI + eoff));
                    ldm_x2(bl[nt], sb + 2u * (BLO + eoff));
                }
#pragma unroll
                for (int mt = 0; mt < 4; mt++) {
                    uint32_t ah[4], al[4];
                    const int eoff = (wm * 64 + mt * 16 + (lane & 15)) * RS
                                   + ks * 16 + (lane >> 4) * 8;
                    ldm_x4(ah, sb + 2u * (AHI + eoff));
                    ldm_x4(al, sb + 2u * (ALO + eoff));
#pragma unroll
                    for (int nt = 0; nt < 4; nt++) {
                        mma_bf16(acc[mt][nt], ah, bh[nt]);
                        mma_bf16(acc[mt][nt], al, bh[nt]);
                        mma_bf16(acc[mt][nt], ah, bl[nt]);
                    }
                }
            }
        }

        // ---- split + STS next tile into other buffer ----
        if (kt + 1 < nkt) {
            const int sn = s ^ 1;
#pragma unroll
            for (int t = 0; t < 4; t++) {
                const int idx = tid + t * 256;
                const int r = idx >> 3, cb = idx & 7;
                const int off = sn * SSTRIDE + r * RS + cb * 4;
                uint2 hi, lo;
                split4(ra[t], hi, lo);
                *(uint2*)(smp + AHI + off) = hi;
                *(uint2*)(smp + ALO + off) = lo;
                split4(rb[t], hi, lo);
                *(uint2*)(smp + BHI + off) = hi;
                *(uint2*)(smp + BLO + off) = lo;
            }
        }
        __syncthreads();
    }

    // ---- epilogue: bias + store ----
#pragma unroll
    for (int mt = 0; mt < 4; mt++) {
        const int rg = m0 + wm * 64 + mt * 16 + (lane >> 2);
#pragma unroll
        for (int nt = 0; nt < 4; nt++) {
            const int c = n0 + wn * 32 + nt * 8 + (lane & 3) * 2;
            const float b0 = bias[c], b1 = bias[c + 1];
            float2 o0, o1;
            o0.x = acc[mt][nt][0] + b0; o0.y = acc[mt][nt][1] + b1;
            o1.x = acc[mt][nt][2] + b0; o1.y = acc[mt][nt][3] + b1;
            *(float2*)(C + (size_t)rg * N + c) = o0;
            *(float2*)(C + (size_t)(rg + 8) * N + c) = o1;
        }
    }
}

// ===========================================================================
// Causal flash attention, fp32 SIMT (unchanged — next round's target)
// ===========================================================================
__global__ void __launch_bounds__(256) attn_kernel(
    const float* __restrict__ qkv, float* __restrict__ outp)
{
    extern __shared__ float smf[];
    float* Qs = smf;
    float* Ks = smf + 64 * 68;
    float* Vs = smf + 2 * 64 * 68;

    const int tid = threadIdx.x;
    const int ty = tid >> 4;
    const int tx = tid & 15;
    const int r0 = ty * 4;
    const int c0 = tx * 4;

    const int rt = blockIdx.x;
    const int h  = blockIdx.y;
    const int b  = blockIdx.z;
    const int g0 = rt * 64;

    const size_t rowbase = (size_t)b * SEQ * (3 * DMODEL);
    const int qcol = h * DHEAD;
    const int kcol = DMODEL + h * DHEAD;
    const int vcol = 2 * DMODEL + h * DHEAD;

#pragma unroll
    for (int t = 0; t < 4; t++) {
        const int idx = tid + t * 256;
        const int row = idx >> 4;
        const int cc  = (idx & 15) << 2;
        *(float4*)&Qs[row * 68 + cc] =
            *(const float4*)(qkv + rowbase + (size_t)(g0 + row) * (3 * DMODEL) + qcol + cc);
    }

    float m[4], l[4], o[4][4];
#pragma unroll
    for (int i = 0; i < 4; i++) {
        m[i] = -CUDART_INF_F; l[i] = 0.f;
#pragma unroll
        for (int j = 0; j < 4; j++) o[i][j] = 0.f;
    }

    for (int jt = 0; jt <= rt; jt++) {
        const int j0 = jt * 64;
        __syncthreads();
#pragma unroll
        for (int t = 0; t < 4; t++) {
            const int idx = tid + t * 256;
            const int row = idx >> 4;
            const int cc  = (idx & 15) << 2;
            const size_t base = rowbase + (size_t)(j0 + row) * (3 * DMODEL);
            *(float4*)&Ks[row * 68 + cc] = *(const float4*)(qkv + base + kcol + cc);
            *(float4*)&Vs[row * 64 + cc] = *(const float4*)(qkv + base + vcol + cc);
        }
        __syncthreads();

        float s[4][4];
#pragma unroll
        for (int i = 0; i < 4; i++)
#pragma unroll
            for (int j = 0; j < 4; j++) s[i][j] = 0.f;

#pragma unroll 4
        for (int kk = 0; kk < 64; kk += 4) {
            float4 a[4], bb[4];
#pragma unroll
            for (int i = 0; i < 4; i++) a[i]  = *(const float4*)&Qs[(r0 + i) * 68 + kk];
#pragma unroll
            for (int j = 0; j < 4; j++) bb[j] = *(const float4*)&Ks[(c0 + j) * 68 + kk];
#pragma unroll
            for (int i = 0; i < 4; i++)
#pragma unroll
                for (int j = 0; j < 4; j++) {
                    s[i][j] = fmaf(a[i].x, bb[j].x, s[i][j]);
                    s[i][j] = fmaf(a[i].y, bb[j].y, s[i][j]);
                    s[i][j] = fmaf(a[i].z, bb[j].z, s[i][j]);
                    s[i][j] = fmaf(a[i].w, bb[j].w, s[i][j]);
                }
        }

        const bool diag = (jt == rt);
#pragma unroll
        for (int i = 0; i < 4; i++)
#pragma unroll
            for (int j = 0; j < 4; j++) {
                float v = s[i][j] * 8.0f;
                if (diag && (j0 + c0 + j > g0 + r0 + i)) v = NEG_VAL;
                s[i][j] = v;
            }

        __syncthreads();

        float p[4][4];
#pragma unroll
        for (int i = 0; i < 4; i++) {
            float mx = fmaxf(fmaxf(s[i][0], s[i][1]), fmaxf(s[i][2], s[i][3]));
#pragma unroll
            for (int off = 8; off; off >>= 1)
                mx = fmaxf(mx, __shfl_xor_sync(0xffffffffu, mx, off));
            const float mn = fmaxf(m[i], mx);
            const float al = __expf(m[i] - mn);
            float ps = 0.f;
#pragma unroll
            for (int j = 0; j < 4; j++) {
                const float pv = __expf(s[i][j] - mn);
                p[i][j] = pv; ps += pv;
            }
#pragma unroll
            for (int off = 8; off; off >>= 1)
                ps += __shfl_xor_sync(0xffffffffu, ps, off);
            l[i] = l[i] * al + ps;
            m[i] = mn;
#pragma unroll
            for (int j = 0; j < 4; j++) o[i][j] *= al;
        }

#pragma unroll
        for (int i = 0; i < 4; i++)
            *(float4*)&Ks[(r0 + i) * 68 + c0] =
                make_float4(p[i][0], p[i][1], p[i][2], p[i][3]);
        __syncthreads();

#pragma unroll 4
        for (int kk = 0; kk < 64; kk += 4) {
            float4 pr[4], vv[4];
#pragma unroll
            for (int i = 0; i < 4; i++) pr[i] = *(const float4*)&Ks[(r0 + i) * 68 + kk];
#pragma unroll
            for (int t = 0; t < 4; t++) vv[t] = *(const float4*)&Vs[(kk + t) * 64 + c0];
#pragma unroll
            for (int i = 0; i < 4; i++) {
                o[i][0] = fmaf(pr[i].x, vv[0].x, o[i][0]);
                o[i][0] = fmaf(pr[i].y, vv[1].x, o[i][0]);
                o[i][0] = fmaf(pr[i].z, vv[2].x, o[i][0]);
                o[i][0] = fmaf(pr[i].w, vv[3].x, o[i][0]);
                o[i][1] = fmaf(pr[i].x, vv[0].y, o[i][1]);
                o[i][1] = fmaf(pr[i].y, vv[1].y, o[i][1]);
                o[i][1] = fmaf(pr[i].z, vv[2].y, o[i][1]);
                o[i][1] = fmaf(pr[i].w, vv[3].y, o[i][1]);
                o[i][2] = fmaf(pr[i].x, vv[0].z, o[i][2]);
                o[i][2] = fmaf(pr[i].y, vv[1].z, o[i][2]);
                o[i][2] = fmaf(pr[i].z, vv[2].z, o[i][2]);
                o[i][2] = fmaf(pr[i].w, vv[3].z, o[i][2]);
                o[i][3] = fmaf(pr[i].x, vv[0].w, o[i][3]);
                o[i][3] = fmaf(pr[i].y, vv[1].w, o[i][3]);
                o[i][3] = fmaf(pr[i].z, vv[2].w, o[i][3]);
                o[i][3] = fmaf(pr[i].w, vv[3].w, o[i][3]);
            }
        }
    }

#pragma unroll
    for (int i = 0; i < 4; i++) {
        const float inv = 1.0f / l[i];
        const size_t obase = ((size_t)b * SEQ + g0 + r0 + i) * DMODEL + h * DHEAD + c0;
        *(float4*)(outp + obase) =
            make_float4(o[i][0] * inv, o[i][1] * inv, o[i][2] * inv, o[i][3] * inv);
    }
}

// ===========================================================================
extern "C" void kernel_launch(void* const* d_in, const int* in_sizes, int n_in,
                              void* d_out, int out_size)
{
    const float* q     = (const float*)d_in[0];
    const float* k     = (const float*)d_in[1];
    const float* v     = (const float*)d_in[2];
    const float* w_qkv = (const float*)d_in[3];
    const float* b_qkv = (const float*)d_in[4];
    const float* w_out = (const float*)d_in[5];
    const float* b_out = (const float*)d_in[6];
    float* out = (float*)d_out;

    float *qkvp, *attnp;
    cudaGetSymbolAddress((void**)&qkvp, g_qkv);
    cudaGetSymbolAddress((void**)&attnp, g_attn);

    cudaFuncSetAttribute(gemm_mma<true>,
                         cudaFuncAttributeMaxDynamicSharedMemorySize, GEMM_SMEM);
    cudaFuncSetAttribute(gemm_mma<false>,
                         cudaFuncAttributeMaxDynamicSharedMemorySize, GEMM_SMEM);
    cudaFuncSetAttribute(attn_kernel,
                         cudaFuncAttributeMaxDynamicSharedMemorySize, 51200);

    // 1) QKV projection: (8192 x 3072) = concat(q,k,v) @ w_qkv^T + b_qkv
    {
        dim3 g(3 * DMODEL / BN, (BATCH * SEQ) / BM);
        gemm_mma<true><<<g, 256, GEMM_SMEM>>>(q, k, v, w_qkv, b_qkv, qkvp,
                                              BATCH * SEQ, 3 * DMODEL, 3 * DMODEL);
    }

    // 2) Causal flash attention
    {
        dim3 g(SEQ / 64, NHEADS, BATCH);
        attn_kernel<<<g, 256, 51200>>>(qkvp, attnp);
    }

    // 3) Output projection: (8192 x 1024) @ w_out^T + b_out
    {
        dim3 g(DMODEL / BN, (BATCH * SEQ) / BM);
        gemm_mma<false><<<g, 256, GEMM_SMEM>>>(attnp, nullptr, nullptr, w_out, b_out, out,
                                               BATCH * SEQ, DMODEL, DMODEL);
    }
}

// round 5
// speedup vs baseline: 2.7273x; 1.8373x over previous
#include <cuda_runtime.h>
#include <cuda_bf16.h>
#include <math_constants.h>
#include <cstdint>

#define BATCH 4
#define SEQ   2048
#define DMODEL 1024
#define NHEADS 16
#define DHEAD 64
#define NEG_VAL (-32767.0f)
#define MTOT  (BATCH * SEQ)      // 8192
#define K3    (3 * DMODEL)       // 3072

typedef __nv_bfloat16 bf16;

// ---- global scratch (bf16 hi/lo split operands) ----
__device__ bf16 g_in_hi[(size_t)MTOT * K3];
__device__ bf16 g_in_lo[(size_t)MTOT * K3];
__device__ bf16 g_wqkv_hi[(size_t)K3 * K3];
__device__ bf16 g_wqkv_lo[(size_t)K3 * K3];
__device__ bf16 g_qkv_hi[(size_t)MTOT * K3];
__device__ bf16 g_qkv_lo[(size_t)MTOT * K3];
__device__ bf16 g_attn_hi[(size_t)MTOT * DMODEL];
__device__ bf16 g_attn_lo[(size_t)MTOT * DMODEL];
__device__ bf16 g_wout_hi[(size_t)DMODEL * DMODEL];
__device__ bf16 g_wout_lo[(size_t)DMODEL * DMODEL];

// ===========================================================================
// helpers
// ===========================================================================
__device__ __forceinline__ uint32_t smem_u32(const void* p) {
    uint32_t a;
    asm("{ .reg .u64 t; cvta.to.shared.u64 t, %1; cvt.u32.u64 %0, t; }"
        : "=r"(a) : "l"(p));
    return a;
}
__device__ __forceinline__ void ldm_x4(uint32_t* r, uint32_t addr) {
    asm volatile("ldmatrix.sync.aligned.m8n8.x4.shared.b16 {%0,%1,%2,%3}, [%4];"
                 : "=r"(r[0]), "=r"(r[1]), "=r"(r[2]), "=r"(r[3]) : "r"(addr));
}
__device__ __forceinline__ void ldm_x2(uint32_t* r, uint32_t addr) {
    asm volatile("ldmatrix.sync.aligned.m8n8.x2.shared.b16 {%0,%1}, [%2];"
                 : "=r"(r[0]), "=r"(r[1]) : "r"(addr));
}
__device__ __forceinline__ void ldm_x2t(uint32_t* r, uint32_t addr) {
    asm volatile("ldmatrix.sync.aligned.m8n8.x2.trans.shared.b16 {%0,%1}, [%2];"
                 : "=r"(r[0]), "=r"(r[1]) : "r"(addr));
}
__device__ __forceinline__ void mma_bf16(float* c, const uint32_t* a, const uint32_t* b) {
    asm volatile(
        "mma.sync.aligned.m16n8k16.row.col.f32.bf16.bf16.f32 "
        "{%0,%1,%2,%3}, {%4,%5,%6,%7}, {%8,%9}, {%0,%1,%2,%3};"
        : "+f"(c[0]), "+f"(c[1]), "+f"(c[2]), "+f"(c[3])
        : "r"(a[0]), "r"(a[1]), "r"(a[2]), "r"(a[3]), "r"(b[0]), "r"(b[1]));
}
__device__ __forceinline__ uint32_t packb(bf16 a, bf16 b) {
    uint16_t ua = *(uint16_t*)&a, ub = *(uint16_t*)&b;
    return (uint32_t)ua | ((uint32_t)ub << 16);
}
__device__ __forceinline__ void split4(float4 v, uint2& hi, uint2& lo) {
    bf16 hx = __float2bfloat16_rn(v.x);
    bf16 hy = __float2bfloat16_rn(v.y);
    bf16 hz = __float2bfloat16_rn(v.z);
    bf16 hw = __float2bfloat16_rn(v.w);
    bf16 lx = __float2bfloat16_rn(v.x - __bfloat162float(hx));
    bf16 ly = __float2bfloat16_rn(v.y - __bfloat162float(hy));
    bf16 lz = __float2bfloat16_rn(v.z - __bfloat162float(hz));
    bf16 lw = __float2bfloat16_rn(v.w - __bfloat162float(hw));
    hi.x = packb(hx, hy); hi.y = packb(hz, hw);
    lo.x = packb(lx, ly); lo.y = packb(lz, lw);
}
__device__ __forceinline__ void cp16(uint32_t s, const void* g) {
    asm volatile("cp.async.cg.shared.global [%0], [%1], 16;" :: "r"(s), "l"(g));
}

// ===========================================================================
// split kernels
// ===========================================================================
__global__ void __launch_bounds__(256) split_concat(
    const float* __restrict__ q, const float* __restrict__ k,
    const float* __restrict__ v, bf16* __restrict__ hi, bf16* __restrict__ lo)
{
    const int idx = blockIdx.x * 256 + threadIdx.x;        // float4 index
    const int row = idx / 768;
    const int rem = idx - row * 768;                        // 0..767
    const int seg = rem >> 8;
    const int cin = rem & 255;
    const float* src = (seg == 0) ? q : ((seg == 1) ? k : v);
    float4 val = *(const float4*)(src + (size_t)row * DMODEL + cin * 4);
    uint2 h, l;
    split4(val, h, l);
    const size_t de = (size_t)row * K3 + rem * 4;
    *(uint2*)(hi + de) = h;
    *(uint2*)(lo + de) = l;
}

__global__ void __launch_bounds__(256) split_plain(
    const float* __restrict__ src, bf16* __restrict__ hi, bf16* __restrict__ lo)
{
    const size_t idx = (size_t)(blockIdx.x * 256 + threadIdx.x) * 4;
    float4 val = *(const float4*)(src + idx);
    uint2 h, l;
    split4(val, h, l);
    *(uint2*)(hi + idx) = h;
    *(uint2*)(lo + idx) = l;
}

// ===========================================================================
// Pure-bf16 mma GEMM with cp.async double buffering.
// C[M,N] = (Ahi+Alo)[M,K] @ (Bhi+Blo)[N,K]^T + bias   (3-product compensation)
// BM=BN=128, BK=32, 256 threads (2x4 warps, warp tile 64x32), 2 CTAs/SM.
// OMODE 0: fp32 C.  OMODE 1: bf16 hi/lo dual outputs.
// ===========================================================================
#define G_STAGE 40960
#define G_AHI 0
#define G_ALO 10240
#define G_BHI 20480
#define G_BLO 30720
#define GEMM_SMEM (2 * G_STAGE)

template <int OMODE>
__global__ void __launch_bounds__(256, 2) gemm_bf16(
    const bf16* __restrict__ Ahi, const bf16* __restrict__ Alo,
    const bf16* __restrict__ Bhi, const bf16* __restrict__ Blo,
    const float* __restrict__ bias,
    float* __restrict__ C, bf16* __restrict__ Chi, bf16* __restrict__ Clo,
    int M, int N, int K)
{
    extern __shared__ __align__(128) char smraw[];
    const uint32_t smb = smem_u32(smraw);
    const int tid = threadIdx.x, lane = tid & 31, wid = tid >> 5;
    const int wm = wid & 1, wn = wid >> 1;
    const int m0 = blockIdx.y * 128, n0 = blockIdx.x * 128;

    float acc[4][4][4];
#pragma unroll
    for (int i = 0; i < 4; i++)
#pragma unroll
        for (int j = 0; j < 4; j++)
#pragma unroll
            for (int e = 0; e < 4; e++) acc[i][j][e] = 0.f;

    const int nkt = K >> 5;

    // prologue prefetch (stage 0)
    {
        const uint32_t sb = smb;
#pragma unroll
        for (int t = 0; t < 2; t++) {
            const int idx = tid + t * 256;
            const int row = idx >> 2;
            const int c8 = (idx & 3) << 3;
            const uint32_t doff = (uint32_t)(row * 40 + c8) * 2;
            const size_t ga = (size_t)(m0 + row) * K + c8;
            cp16(sb + G_AHI + doff, Ahi + ga);
            cp16(sb + G_ALO + doff, Alo + ga);
            const size_t gb = (size_t)(n0 + row) * K + c8;
            cp16(sb + G_BHI + doff, Bhi + gb);
            cp16(sb + G_BLO + doff, Blo + gb);
        }
        asm volatile("cp.async.commit_group;");
    }

    for (int kt = 0; kt < nkt; kt++) {
        if (kt + 1 < nkt) {
            const int k0 = (kt + 1) << 5;
            const uint32_t sb = smb + ((kt + 1) & 1) * G_STAGE;
#pragma unroll
            for (int t = 0; t < 2; t++) {
                const int idx = tid + t * 256;
                const int row = idx >> 2;
                const int c8 = (idx & 3) << 3;
                const uint32_t doff = (uint32_t)(row * 40 + c8) * 2;
                const size_t ga = (size_t)(m0 + row) * K + k0 + c8;
                cp16(sb + G_AHI + doff, Ahi + ga);
                cp16(sb + G_ALO + doff, Alo + ga);
                const size_t gb = (size_t)(n0 + row) * K + k0 + c8;
                cp16(sb + G_BHI + doff, Bhi + gb);
                cp16(sb + G_BLO + doff, Blo + gb);
            }
            asm volatile("cp.async.commit_group;");
            asm volatile("cp.async.wait_group 1;");
        } else {
            asm volatile("cp.async.wait_group 0;");
        }
        __syncthreads();

        const uint32_t sb = smb + (kt & 1) * G_STAGE;
#pragma unroll
        for (int ks = 0; ks < 2; ks++) {
            uint32_t bh[4][2], bl[4][2];
#pragma unroll
            for (int nt = 0; nt < 4; nt++) {
                const uint32_t eo =
                    (uint32_t)((wn * 32 + nt * 8 + (lane & 7)) * 40
                               + ks * 16 + ((lane >> 3) & 1) * 8) * 2;
                ldm_x2(bh[nt], sb + G_BHI + eo);
                ldm_x2(bl[nt], sb + G_BLO + eo);
            }
#pragma unroll
            for (int mt = 0; mt < 4; mt++) {
                uint32_t ah[4], al[4];
                const uint32_t eo =
                    (uint32_t)((wm * 64 + mt * 16 + (lane & 15)) * 40
                               + ks * 16 + ((lane >> 4) & 1) * 8) * 2;
                ldm_x4(ah, sb + G_AHI + eo);
                ldm_x4(al, sb + G_ALO + eo);
#pragma unroll
                for (int nt = 0; nt < 4; nt++) {
                    mma_bf16(acc[mt][nt], ah, bh[nt]);
                    mma_bf16(acc[mt][nt], al, bh[nt]);
                    mma_bf16(acc[mt][nt], ah, bl[nt]);
                }
            }
        }
        __syncthreads();
    }

    // epilogue
#pragma unroll
    for (int mt = 0; mt < 4; mt++) {
        const int rg = m0 + wm * 64 + mt * 16 + (lane >> 2);
#pragma unroll
        for (int nt = 0; nt < 4; nt++) {
            const int c = n0 + wn * 32 + nt * 8 + (lane & 3) * 2;
            const float b0 = bias[c], b1 = bias[c + 1];
            const float v00 = acc[mt][nt][0] + b0, v01 = acc[mt][nt][1] + b1;
            const float v10 = acc[mt][nt][2] + b0, v11 = acc[mt][nt][3] + b1;
            if (OMODE == 0) {
                *(float2*)(C + (size_t)rg * N + c)       = make_float2(v00, v01);
                *(float2*)(C + (size_t)(rg + 8) * N + c) = make_float2(v10, v11);
            } else {
                bf16 h00 = __float2bfloat16_rn(v00), h01 = __float2bfloat16_rn(v01);
                bf16 h10 = __float2bfloat16_rn(v10), h11 = __float2bfloat16_rn(v11);
                bf16 l00 = __float2bfloat16_rn(v00 - __bfloat162float(h00));
                bf16 l01 = __float2bfloat16_rn(v01 - __bfloat162float(h01));
                bf16 l10 = __float2bfloat16_rn(v10 - __bfloat162float(h10));
                bf16 l11 = __float2bfloat16_rn(v11 - __bfloat162float(h11));
                ((uint32_t*)Chi)[((size_t)rg * N + c) >> 1]       = packb(h00, h01);
                ((uint32_t*)Clo)[((size_t)rg * N + c) >> 1]       = packb(l00, l01);
                ((uint32_t*)Chi)[((size_t)(rg + 8) * N + c) >> 1] = packb(h10, h11);
                ((uint32_t*)Clo)[((size_t)(rg + 8) * N + c) >> 1] = packb(l10, l11);
            }
        }
    }
}

// ===========================================================================
// Tensor-core causal flash attention.
// CTA = (128 q-rows, head, batch); 8 warps, each owns 16 q-rows x full KV tile.
// KV tile = 64. S via hi/lo bf16 mma (3 products); P kept in registers and
// re-packed into A-fragments for PV (hi/lo, 3 products); V via ldmatrix.trans.
// ===========================================================================
#define QRS 72
#define ARS 72
#define SQHI 0
#define SQLO 9216
#define SKHI 18432
#define SKLO 23040
#define SVHI 27648
#define SVLO 32256
#define ATTN_SMEM (36864 * 2)

__global__ void __launch_bounds__(256, 2) attn_mma(
    const bf16* __restrict__ qkv_hi, const bf16* __restrict__ qkv_lo,
    bf16* __restrict__ ohi, bf16* __restrict__ olo)
{
    extern __shared__ __align__(128) char smraw[];
    bf16* smp = (bf16*)smraw;
    const uint32_t smb = smem_u32(smraw);
    const int tid = threadIdx.x, lane = tid & 31, wid = tid >> 5;
    const int gid = lane >> 2, tig = lane & 3;
    const int bt = blockIdx.x, h = blockIdx.y, b = blockIdx.z;
    const int g0 = bt * 128;

    // load Q tile (128 x 64) hi/lo
    const size_t qgbase = ((size_t)b * SEQ + g0) * K3 + h * 64;
#pragma unroll
    for (int t = 0; t < 8; t++) {
        const int idx = tid + t * 256;
        const int row = idx >> 4;
        const int c4 = (idx & 15) * 4;
        *(uint2*)(smp + SQHI + row * QRS + c4) =
            *(const uint2*)(qkv_hi + qgbase + (size_t)row * K3 + c4);
        *(uint2*)(smp + SQLO + row * QRS + c4) =
            *(const uint2*)(qkv_lo + qgbase + (size_t)row * K3 + c4);
    }

    float oacc[8][4];
#pragma unroll
    for (int i = 0; i < 8; i++)
#pragma unroll
        for (int e = 0; e < 4; e++) oacc[i][e] = 0.f;
    float mA = -CUDART_INF_F, mB = -CUDART_INF_F, lA = 0.f, lB = 0.f;

    const int wrow = g0 + wid * 16;       // warp's first q row
    const int rA = wrow + gid;            // this thread's row A (row B = rA+8)
    const int jtmax = 2 * bt + 1;

    for (int jt = 0; jt <= jtmax; jt++) {
        const int j0 = jt * 64;
        __syncthreads();
        // load K,V tiles (64 x 64) hi/lo
        const size_t kvbase = ((size_t)b * SEQ + j0) * K3 + h * 64;
#pragma unroll
        for (int t = 0; t < 4; t++) {
            const int idx = tid + t * 256;
            const int row = idx >> 4;
            const int c4 = (idx & 15) * 4;
            const size_t gk = kvbase + (size_t)row * K3 + DMODEL + c4;
            const size_t gv = kvbase + (size_t)row * K3 + 2 * DMODEL + c4;
            *(uint2*)(smp + SKHI + row * ARS + c4) = *(const uint2*)(qkv_hi + gk);
            *(uint2*)(smp + SKLO + row * ARS + c4) = *(const uint2*)(qkv_lo + gk);
            *(uint2*)(smp + SVHI + row * ARS + c4) = *(const uint2*)(qkv_hi + gv);
            *(uint2*)(smp + SVLO + row * ARS + c4) = *(const uint2*)(qkv_lo + gv);
        }
        __syncthreads();

        // ---- S = Q @ K^T ----
        float sacc[8][4];
#pragma unroll
        for (int i = 0; i < 8; i++)
#pragma unroll
            for (int e = 0; e < 4; e++) sacc[i][e] = 0.f;

#pragma unroll
        for (int ks = 0; ks < 4; ks++) {
            uint32_t ah[4], al[4];
            const uint32_t eo =
                (uint32_t)((wid * 16 + (lane & 15)) * QRS
                           + ks * 16 + ((lane >> 4) & 1) * 8) * 2;
            ldm_x4(ah, smb + SQHI * 2 + eo);
            ldm_x4(al, smb + SQLO * 2 + eo);
#pragma unroll
            for (int nf = 0; nf < 8; nf++) {
                uint32_t bh[2], bl[2];
                const uint32_t eb =
                    (uint32_t)((nf * 8 + (lane & 7)) * ARS
                               + ks * 16 + ((lane >> 3) & 1) * 8) * 2;
                ldm_x2(bh, smb + SKHI * 2 + eb);
                ldm_x2(bl, smb + SKLO * 2 + eb);
                mma_bf16(sacc[nf], ah, bh);
                mma_bf16(sacc[nf], al, bh);
                mma_bf16(sacc[nf], ah, bl);
            }
        }

        // ---- scale + causal mask ----
        const bool needmask = (j0 + 63 > wrow);
#pragma unroll
        for (int nf = 0; nf < 8; nf++) {
#pragma unroll
            for (int e = 0; e < 4; e++) {
                float vsc = sacc[nf][e] * 8.0f;
                if (needmask) {
                    const int col = j0 + nf * 8 + tig * 2 + (e & 1);
                    const int row = (e < 2) ? rA : (rA + 8);
                    if (col > row) vsc = NEG_VAL;
                }
                sacc[nf][e] = vsc;
            }
        }

        // ---- online softmax ----
        float mxA = -CUDART_INF_F, mxB = -CUDART_INF_F;
#pragma unroll
        for (int nf = 0; nf < 8; nf++) {
            mxA = fmaxf(mxA, fmaxf(sacc[nf][0], sacc[nf][1]));
            mxB = fmaxf(mxB, fmaxf(sacc[nf][2], sacc[nf][3]));
        }
        mxA = fmaxf(mxA, __shfl_xor_sync(0xffffffffu, mxA, 1));
        mxA = fmaxf(mxA, __shfl_xor_sync(0xffffffffu, mxA, 2));
        mxB = fmaxf(mxB, __shfl_xor_sync(0xffffffffu, mxB, 1));
        mxB = fmaxf(mxB, __shfl_xor_sync(0xffffffffu, mxB, 2));

        const float mnA = fmaxf(mA, mxA), mnB = fmaxf(mB, mxB);
        const float alA = __expf(mA - mnA), alB = __expf(mB - mnB);

        float psA = 0.f, psB = 0.f;
        uint32_t phiA[8], phiB[8], ploA[8], ploB[8];
#pragma unroll
        for (int nf = 0; nf < 8; nf++) {
            const float p0 = __expf(sacc[nf][0] - mnA);
            const float p1 = __expf(sacc[nf][1] - mnA);
            const float p2 = __expf(sacc[nf][2] - mnB);
            const float p3 = __expf(sacc[nf][3] - mnB);
            psA += p0 + p1; psB += p2 + p3;
            bf16 h0 = __float2bfloat16_rn(p0), h1 = __float2bfloat16_rn(p1);
            bf16 h2 = __float2bfloat16_rn(p2), h3 = __float2bfloat16_rn(p3);
            phiA[nf] = packb(h0, h1);
            phiB[nf] = packb(h2, h3);
            ploA[nf] = packb(__float2bfloat16_rn(p0 - __bfloat162float(h0)),
                             __float2bfloat16_rn(p1 - __bfloat162float(h1)));
            ploB[nf] = packb(__float2bfloat16_rn(p2 - __bfloat162float(h2)),
                             __float2bfloat16_rn(p3 - __bfloat162float(h3)));
        }
        psA += __shfl_xor_sync(0xffffffffu, psA, 1);
        psA += __shfl_xor_sync(0xffffffffu, psA, 2);
        psB += __shfl_xor_sync(0xffffffffu, psB, 1);
        psB += __shfl_xor_sync(0xffffffffu, psB, 2);

        lA = lA * alA + psA; lB = lB * alB + psB;
        mA = mnA; mB = mnB;
#pragma unroll
        for (int nt = 0; nt < 8; nt++) {
            oacc[nt][0] *= alA; oacc[nt][1] *= alA;
            oacc[nt][2] *= alB; oacc[nt][3] *= alB;
        }

        // ---- O += P @ V ----
#pragma unroll
        for (int kc = 0; kc < 4; kc++) {
            uint32_t ah[4] = { phiA[2 * kc], phiB[2 * kc],
                               phiA[2 * kc + 1], phiB[2 * kc + 1] };
            uint32_t al[4] = { ploA[2 * kc], ploB[2 * kc],
                               ploA[2 * kc + 1], ploB[2 * kc + 1] };
#pragma unroll
            for (int nt = 0; nt < 8; nt++) {
                uint32_t bh[2], bl[2];
                const uint32_t ev =
                    (uint32_t)((kc * 16 + (lane & 15)) * ARS + nt * 8) * 2;
                ldm_x2t(bh, smb + SVHI * 2 + ev);
                ldm_x2t(bl, smb + SVLO * 2 + ev);
                mma_bf16(oacc[nt], ah, bh);
                mma_bf16(oacc[nt], al, bh);
                mma_bf16(oacc[nt], ah, bl);
            }
        }
    }

    // ---- epilogue: O/l, split to bf16 hi/lo ----
    const float ivA = 1.f / lA, ivB = 1.f / lB;
    const size_t gra = (size_t)b * SEQ + rA;
#pragma unroll
    for (int nt = 0; nt < 8; nt++) {
        const int col = h * 64 + nt * 8 + tig * 2;
        const float v0 = oacc[nt][0] * ivA, v1 = oacc[nt][1] * ivA;
        const float v2 = oacc[nt][2] * ivB, v3 = oacc[nt][3] * ivB;
        bf16 h0 = __float2bfloat16_rn(v0), h1 = __float2bfloat16_rn(v1);
        bf16 h2 = __float2bfloat16_rn(v2), h3 = __float2bfloat16_rn(v3);
        const size_t iA = (gra * DMODEL + col) >> 1;
        const size_t iB = ((gra + 8) * DMODEL + col) >> 1;
        ((uint32_t*)ohi)[iA] = packb(h0, h1);
        ((uint32_t*)olo)[iA] = packb(__float2bfloat16_rn(v0 - __bfloat162float(h0)),
                                     __float2bfloat16_rn(v1 - __bfloat162float(h1)));
        ((uint32_t*)ohi)[iB] = packb(h2, h3);
        ((uint32_t*)olo)[iB] = packb(__float2bfloat16_rn(v2 - __bfloat162float(h2)),
                                     __float2bfloat16_rn(v3 - __bfloat162float(h3)));
    }
}

// ===========================================================================
extern "C" void kernel_launch(void* const* d_in, const int* in_sizes, int n_in,
                              void* d_out, int out_size)
{
    const float* q     = (const float*)d_in[0];
    const float* k     = (const float*)d_in[1];
    const float* v     = (const float*)d_in[2];
    const float* w_qkv = (const float*)d_in[3];
    const float* b_qkv = (const float*)d_in[4];
    const float* w_out = (const float*)d_in[5];
    const float* b_out = (const float*)d_in[6];
    float* out = (float*)d_out;

    bf16 *in_hi, *in_lo, *wqkv_hi, *wqkv_lo, *qkv_hi, *qkv_lo;
    bf16 *attn_hi, *attn_lo, *wout_hi, *wout_lo;
    cudaGetSymbolAddress((void**)&in_hi,   g_in_hi);
    cudaGetSymbolAddress((void**)&in_lo,   g_in_lo);
    cudaGetSymbolAddress((void**)&wqkv_hi, g_wqkv_hi);
    cudaGetSymbolAddress((void**)&wqkv_lo, g_wqkv_lo);
    cudaGetSymbolAddress((void**)&qkv_hi,  g_qkv_hi);
    cudaGetSymbolAddress((void**)&qkv_lo,  g_qkv_lo);
    cudaGetSymbolAddress((void**)&attn_hi, g_attn_hi);
    cudaGetSymbolAddress((void**)&attn_lo, g_attn_lo);
    cudaGetSymbolAddress((void**)&wout_hi, g_wout_hi);
    cudaGetSymbolAddress((void**)&wout_lo, g_wout_lo);

    cudaFuncSetAttribute(gemm_bf16<0>,
                         cudaFuncAttributeMaxDynamicSharedMemorySize, GEMM_SMEM);
    cudaFuncSetAttribute(gemm_bf16<1>,
                         cudaFuncAttributeMaxDynamicSharedMemorySize, GEMM_SMEM);
    cudaFuncSetAttribute(attn_mma,
                         cudaFuncAttributeMaxDynamicSharedMemorySize, ATTN_SMEM);

    // 0) splits
    split_concat<<<(MTOT * K3 / 4) / 256, 256>>>(q, k, v, in_hi, in_lo);
    split_plain<<<(K3 * K3 / 4) / 256, 256>>>(w_qkv, wqkv_hi, wqkv_lo);
    split_plain<<<(DMODEL * DMODEL / 4) / 256, 256>>>(w_out, wout_hi, wout_lo);

    // 1) QKV projection -> bf16 hi/lo qkv
    {
        dim3 g(K3 / 128, MTOT / 128);
        gemm_bf16<1><<<g, 256, GEMM_SMEM>>>(in_hi, in_lo, wqkv_hi, wqkv_lo,
                                            b_qkv, nullptr, qkv_hi, qkv_lo,
                                            MTOT, K3, K3);
    }

    // 2) attention -> bf16 hi/lo attn
    {
        dim3 g(SEQ / 128, NHEADS, BATCH);
        attn_mma<<<g, 256, ATTN_SMEM>>>(qkv_hi, qkv_lo, attn_hi, attn_lo);
    }

    // 3) output projection -> fp32 out
    {
        dim3 g(DMODEL / 128, MTOT / 128);
        gemm_bf16<0><<<g, 256, GEMM_SMEM>>>(attn_hi, attn_lo, wout_hi, wout_lo,
                                            b_out, out, nullptr, nullptr,
                                            MTOT, DMODEL, DMODEL);
    }
}

// round 6
// speedup vs baseline: 2.8959x; 1.0618x over previous
#include <cuda_runtime.h>
#include <cuda_bf16.h>
#include <math_constants.h>
#include <cstdint>

#define BATCH 4
#define SEQ   2048
#define DMODEL 1024
#define NHEADS 16
#define DHEAD 64
#define NEG_VAL (-32767.0f)
#define MTOT  (BATCH * SEQ)      // 8192
#define K3    (3 * DMODEL)       // 3072

typedef __nv_bfloat16 bf16;

// ---- global scratch (bf16 hi/lo split operands) ----
__device__ bf16 g_in_hi[(size_t)MTOT * K3];
__device__ bf16 g_in_lo[(size_t)MTOT * K3];
__device__ bf16 g_wqkv_hi[(size_t)K3 * K3];
__device__ bf16 g_wqkv_lo[(size_t)K3 * K3];
__device__ bf16 g_qkv_hi[(size_t)MTOT * K3];
__device__ bf16 g_qkv_lo[(size_t)MTOT * K3];
__device__ bf16 g_attn_hi[(size_t)MTOT * DMODEL];
__device__ bf16 g_attn_lo[(size_t)MTOT * DMODEL];
__device__ bf16 g_wout_hi[(size_t)DMODEL * DMODEL];
__device__ bf16 g_wout_lo[(size_t)DMODEL * DMODEL];

// ===========================================================================
// helpers
// ===========================================================================
__device__ __forceinline__ uint32_t smem_u32(const void* p) {
    uint32_t a;
    asm("{ .reg .u64 t; cvta.to.shared.u64 t, %1; cvt.u32.u64 %0, t; }"
        : "=r"(a) : "l"(p));
    return a;
}
__device__ __forceinline__ void ldm_x4(uint32_t* r, uint32_t addr) {
    asm volatile("ldmatrix.sync.aligned.m8n8.x4.shared.b16 {%0,%1,%2,%3}, [%4];"
                 : "=r"(r[0]), "=r"(r[1]), "=r"(r[2]), "=r"(r[3]) : "r"(addr));
}
__device__ __forceinline__ void ldm_x4t(uint32_t* r, uint32_t addr) {
    asm volatile("ldmatrix.sync.aligned.m8n8.x4.trans.shared.b16 {%0,%1,%2,%3}, [%4];"
                 : "=r"(r[0]), "=r"(r[1]), "=r"(r[2]), "=r"(r[3]) : "r"(addr));
}
__device__ __forceinline__ void mma_bf16(float* c, const uint32_t* a, const uint32_t* b) {
    asm volatile(
        "mma.sync.aligned.m16n8k16.row.col.f32.bf16.bf16.f32 "
        "{%0,%1,%2,%3}, {%4,%5,%6,%7}, {%8,%9}, {%0,%1,%2,%3};"
        : "+f"(c[0]), "+f"(c[1]), "+f"(c[2]), "+f"(c[3])
        : "r"(a[0]), "r"(a[1]), "r"(a[2]), "r"(a[3]), "r"(b[0]), "r"(b[1]));
}
__device__ __forceinline__ uint32_t packb(bf16 a, bf16 b) {
    uint16_t ua = *(uint16_t*)&a, ub = *(uint16_t*)&b;
    return (uint32_t)ua | ((uint32_t)ub << 16);
}
__device__ __forceinline__ void split4(float4 v, uint2& hi, uint2& lo) {
    bf16 hx = __float2bfloat16_rn(v.x);
    bf16 hy = __float2bfloat16_rn(v.y);
    bf16 hz = __float2bfloat16_rn(v.z);
    bf16 hw = __float2bfloat16_rn(v.w);
    bf16 lx = __float2bfloat16_rn(v.x - __bfloat162float(hx));
    bf16 ly = __float2bfloat16_rn(v.y - __bfloat162float(hy));
    bf16 lz = __float2bfloat16_rn(v.z - __bfloat162float(hz));
    bf16 lw = __float2bfloat16_rn(v.w - __bfloat162float(hw));
    hi.x = packb(hx, hy); hi.y = packb(hz, hw);
    lo.x = packb(lx, ly); lo.y = packb(lz, lw);
}
__device__ __forceinline__ void cp16(uint32_t s, const void* g) {
    asm volatile("cp.async.cg.shared.global [%0], [%1], 16;" :: "r"(s), "l"(g));
}

// ===========================================================================
// split kernels
// ===========================================================================
__global__ void __launch_bounds__(256) split_concat(
    const float* __restrict__ q, const float* __restrict__ k,
    const float* __restrict__ v, bf16* __restrict__ hi, bf16* __restrict__ lo)
{
    const int idx = blockIdx.x * 256 + threadIdx.x;        // float4 index
    const int row = idx / 768;
    const int rem = idx - row * 768;                        // 0..767
    const int seg = rem >> 8;
    const int cin = rem & 255;
    const float* src = (seg == 0) ? q : ((seg == 1) ? k : v);
    float4 val = *(const float4*)(src + (size_t)row * DMODEL + cin * 4);
    uint2 h, l;
    split4(val, h, l);
    const size_t de = (size_t)row * K3 + rem * 4;
    *(uint2*)(hi + de) = h;
    *(uint2*)(lo + de) = l;
}

__global__ void __launch_bounds__(256) split_plain(
    const float* __restrict__ src, bf16* __restrict__ hi, bf16* __restrict__ lo)
{
    const size_t idx = (size_t)(blockIdx.x * 256 + threadIdx.x) * 4;
    float4 val = *(const float4*)(src + idx);
    uint2 h, l;
    split4(val, h, l);
    *(uint2*)(hi + idx) = h;
    *(uint2*)(lo + idx) = l;
}

// ===========================================================================
// Pure-bf16 mma GEMM, cp.async double buffered, all-x4 ldmatrix.
// ===========================================================================
#define G_STAGE 40960
#define G_AHI 0
#define G_ALO 10240
#define G_BHI 20480
#define G_BLO 30720
#define GEMM_SMEM (2 * G_STAGE)

template <int OMODE>
__global__ void __launch_bounds__(256, 2) gemm_bf16(
    const bf16* __restrict__ Ahi, const bf16* __restrict__ Alo,
    const bf16* __restrict__ Bhi, const bf16* __restrict__ Blo,
    const float* __restrict__ bias,
    float* __restrict__ C, bf16* __restrict__ Chi, bf16* __restrict__ Clo,
    int M, int N, int K)
{
    extern __shared__ __align__(128) char smraw[];
    const uint32_t smb = smem_u32(smraw);
    const int tid = threadIdx.x, lane = tid & 31, wid = tid >> 5;
    const int wm = wid & 1, wn = wid >> 1;
    const int m0 = blockIdx.y * 128, n0 = blockIdx.x * 128;

    float acc[4][4][4];
#pragma unroll
    for (int i = 0; i < 4; i++)
#pragma unroll
        for (int j = 0; j < 4; j++)
#pragma unroll
            for (int e = 0; e < 4; e++) acc[i][j][e] = 0.f;

    const int nkt = K >> 5;

    // prologue prefetch (stage 0)
    {
        const uint32_t sb = smb;
#pragma unroll
        for (int t = 0; t < 2; t++) {
            const int idx = tid + t * 256;
            const int row = idx >> 2;
            const int c8 = (idx & 3) << 3;
            const uint32_t doff = (uint32_t)(row * 40 + c8) * 2;
            const size_t ga = (size_t)(m0 + row) * K + c8;
            cp16(sb + G_AHI + doff, Ahi + ga);
            cp16(sb + G_ALO + doff, Alo + ga);
            const size_t gb = (size_t)(n0 + row) * K + c8;
            cp16(sb + G_BHI + doff, Bhi + gb);
            cp16(sb + G_BLO + doff, Blo + gb);
        }
        asm volatile("cp.async.commit_group;");
    }

    for (int kt = 0; kt < nkt; kt++) {
        if (kt + 1 < nkt) {
            const int k0 = (kt + 1) << 5;
            const uint32_t sb = smb + ((kt + 1) & 1) * G_STAGE;
#pragma unroll
            for (int t = 0; t < 2; t++) {
                const int idx = tid + t * 256;
                const int row = idx >> 2;
                const int c8 = (idx & 3) << 3;
                const uint32_t doff = (uint32_t)(row * 40 + c8) * 2;
                const size_t ga = (size_t)(m0 + row) * K + k0 + c8;
                cp16(sb + G_AHI + doff, Ahi + ga);
                cp16(sb + G_ALO + doff, Alo + ga);
                const size_t gb = (size_t)(n0 + row) * K + k0 + c8;
                cp16(sb + G_BHI + doff, Bhi + gb);
                cp16(sb + G_BLO + doff, Blo + gb);
            }
            asm volatile("cp.async.commit_group;");
            asm volatile("cp.async.wait_group 1;");
        } else {
            asm volatile("cp.async.wait_group 0;");
        }
        __syncthreads();

        const uint32_t sb = smb + (kt & 1) * G_STAGE;
#pragma unroll
        for (int ks = 0; ks < 2; ks++) {
            // B fragments: 2 x4 loads per (hi,lo), each covering 2 n-frags
            uint32_t bh[2][4], bl[2][4];
#pragma unroll
            for (int p = 0; p < 2; p++) {
                const uint32_t row = (uint32_t)(wn * 32 + p * 16 + (lane & 7)
                                                + ((lane >> 4) & 1) * 8);
                const uint32_t kc = (uint32_t)(ks * 16 + ((lane >> 3) & 1) * 8);
                const uint32_t eo = (row * 40 + kc) * 2;
                ldm_x4(bh[p], sb + G_BHI + eo);
                ldm_x4(bl[p], sb + G_BLO + eo);
            }
#pragma unroll
            for (int mt = 0; mt < 4; mt++) {
                uint32_t ah[4], al[4];
                const uint32_t eo =
                    (uint32_t)((wm * 64 + mt * 16 + (lane & 15)) * 40
                               + ks * 16 + ((lane >> 4) & 1) * 8) * 2;
                ldm_x4(ah, sb + G_AHI + eo);
                ldm_x4(al, sb + G_ALO + eo);
#pragma unroll
                for (int p = 0; p < 2; p++)
#pragma unroll
                    for (int hf = 0; hf < 2; hf++) {
                        float* a = acc[mt][p * 2 + hf];
                        mma_bf16(a, ah, &bh[p][hf * 2]);
                        mma_bf16(a, al, &bh[p][hf * 2]);
                        mma_bf16(a, ah, &bl[p][hf * 2]);
                    }
            }
        }
        __syncthreads();
    }

    // epilogue
#pragma unroll
    for (int mt = 0; mt < 4; mt++) {
        const int rg = m0 + wm * 64 + mt * 16 + (lane >> 2);
#pragma unroll
        for (int nt = 0; nt < 4; nt++) {
            const int c = n0 + wn * 32 + nt * 8 + (lane & 3) * 2;
            const float b0 = bias[c], b1 = bias[c + 1];
            const float v00 = acc[mt][nt][0] + b0, v01 = acc[mt][nt][1] + b1;
            const float v10 = acc[mt][nt][2] + b0, v11 = acc[mt][nt][3] + b1;
            if (OMODE == 0) {
                *(float2*)(C + (size_t)rg * N + c)       = make_float2(v00, v01);
                *(float2*)(C + (size_t)(rg + 8) * N + c) = make_float2(v10, v11);
            } else {
                bf16 h00 = __float2bfloat16_rn(v00), h01 = __float2bfloat16_rn(v01);
                bf16 h10 = __float2bfloat16_rn(v10), h11 = __float2bfloat16_rn(v11);
                bf16 l00 = __float2bfloat16_rn(v00 - __bfloat162float(h00));
                bf16 l01 = __float2bfloat16_rn(v01 - __bfloat162float(h01));
                bf16 l10 = __float2bfloat16_rn(v10 - __bfloat162float(h10));
                bf16 l11 = __float2bfloat16_rn(v11 - __bfloat162float(h11));
                ((uint32_t*)Chi)[((size_t)rg * N + c) >> 1]       = packb(h00, h01);
                ((uint32_t*)Clo)[((size_t)rg * N + c) >> 1]       = packb(l00, l01);
                ((uint32_t*)Chi)[((size_t)(rg + 8) * N + c) >> 1] = packb(h10, h11);
                ((uint32_t*)Clo)[((size_t)(rg + 8) * N + c) >> 1] = packb(l10, l11);
            }
        }
    }
}

// ===========================================================================
// Tensor-core causal flash attention with cp.async double-buffered K/V.
// CTA = (128 q-rows, head, batch); 8 warps, warp = 16 q-rows x 64 kv-cols.
// All smem offsets in bf16 elements. K/V row stride 72.
// ===========================================================================
#define SQHI 0
#define SQLO 9216
#define KV0   18432          // stage 0 base
#define KVSTG 18432          // elements per stage
#define OKHI 0
#define OKLO 4608
#define OVHI 9216
#define OVLO 13824
#define ATTN_SMEM ((18432 + 2 * 18432) * 2)   // 110592 bytes

__global__ void __launch_bounds__(256, 2) attn_mma(
    const bf16* __restrict__ qkv_hi, const bf16* __restrict__ qkv_lo,
    bf16* __restrict__ ohi, bf16* __restrict__ olo)
{
    extern __shared__ __align__(128) char smraw[];
    const uint32_t smb = smem_u32(smraw);
    const int tid = threadIdx.x, lane = tid & 31, wid = tid >> 5;
    const int gid = lane >> 2, tig = lane & 3;
    const int bt = blockIdx.x, h = blockIdx.y, b = blockIdx.z;
    const int g0 = bt * 128;
    const int jtmax = 2 * bt + 1;

    // ---- prologue: cp.async Q tile + KV tile 0, one group ----
    {
#pragma unroll
        for (int t = 0; t < 4; t++) {
            const int idx = tid + t * 256;
            const int row = idx >> 3;
            const int c8 = (idx & 7) * 8;
            const size_t g = ((size_t)b * SEQ + g0 + row) * K3 + h * 64 + c8;
            const uint32_t so = (uint32_t)(row * 72 + c8);
            cp16(smb + (SQHI + so) * 2, qkv_hi + g);
            cp16(smb + (SQLO + so) * 2, qkv_lo + g);
        }
#pragma unroll
        for (int t = 0; t < 2; t++) {
            const int idx = tid + t * 256;
            const int row = idx >> 3;
            const int c8 = (idx & 7) * 8;
            const size_t g = ((size_t)b * SEQ + row) * K3 + h * 64 + c8;
            const uint32_t so = KV0 + (uint32_t)(row * 72 + c8);
            cp16(smb + (so + OKHI) * 2, qkv_hi + g + DMODEL);
            cp16(smb + (so + OKLO) * 2, qkv_lo + g + DMODEL);
            cp16(smb + (so + OVHI) * 2, qkv_hi + g + 2 * DMODEL);
            cp16(smb + (so + OVLO) * 2, qkv_lo + g + 2 * DMODEL);
        }
        asm volatile("cp.async.commit_group;");
    }

    float oacc[8][4];
#pragma unroll
    for (int i = 0; i < 8; i++)
#pragma unroll
        for (int e = 0; e < 4; e++) oacc[i][e] = 0.f;
    float mA = -CUDART_INF_F, mB = -CUDART_INF_F, lA = 0.f, lB = 0.f;

    const int wrow = g0 + wid * 16;
    const int rA = wrow + gid;

    for (int jt = 0; jt <= jtmax; jt++) {
        // prefetch next KV tile
        if (jt + 1 <= jtmax) {
            const int j1 = (jt + 1) * 64;
            const uint32_t stg = KV0 + ((jt + 1) & 1) * KVSTG;
#pragma unroll
            for (int t = 0; t < 2; t++) {
                const int idx = tid + t * 256;
                const int row = idx >> 3;
                const int c8 = (idx & 7) * 8;
                const size_t g = ((size_t)b * SEQ + j1 + row) * K3 + h * 64 + c8;
                const uint32_t so = stg + (uint32_t)(row * 72 + c8);
                cp16(smb + (so + OKHI) * 2, qkv_hi + g + DMODEL);
                cp16(smb + (so + OKLO) * 2, qkv_lo + g + DMODEL);
                cp16(smb + (so + OVHI) * 2, qkv_hi + g + 2 * DMODEL);
                cp16(smb + (so + OVLO) * 2, qkv_lo + g + 2 * DMODEL);
            }
            asm volatile("cp.async.commit_group;");
            asm volatile("cp.async.wait_group 1;");
        } else {
            asm volatile("cp.async.wait_group 0;");
        }
        __syncthreads();

        const uint32_t kst = KV0 + (jt & 1) * KVSTG;
        const int j0 = jt * 64;

        // ---- S = Q @ K^T (hi/lo 3-product) ----
        float sacc[8][4];
#pragma unroll
        for (int i = 0; i < 8; i++)
#pragma unroll
            for (int e = 0; e < 4; e++) sacc[i][e] = 0.f;

#pragma unroll
        for (int ks = 0; ks < 4; ks++) {
            uint32_t ah[4], al[4];
            const uint32_t eo =
                (uint32_t)((wid * 16 + (lane & 15)) * 72
                           + ks * 16 + ((lane >> 4) & 1) * 8) * 2;
            ldm_x4(ah, smb + SQHI * 2 + eo);
            ldm_x4(al, smb + SQLO * 2 + eo);
#pragma unroll
            for (int pf = 0; pf < 4; pf++) {
                uint32_t bh[4], bl[4];
                const uint32_t row = (uint32_t)(pf * 16 + (lane & 7)
                                                + ((lane >> 4) & 1) * 8);
                const uint32_t kc = (uint32_t)(ks * 16 + ((lane >> 3) & 1) * 8);
                const uint32_t eb = (row * 72 + kc) * 2;
                ldm_x4(bh, smb + (kst + OKHI) * 2 + eb);
                ldm_x4(bl, smb + (kst + OKLO) * 2 + eb);
#pragma unroll
                for (int hf = 0; hf < 2; hf++) {
                    float* sa = sacc[pf * 2 + hf];
                    mma_bf16(sa, ah, &bh[hf * 2]);
                    mma_bf16(sa, al, &bh[hf * 2]);
                    mma_bf16(sa, ah, &bl[hf * 2]);
                }
            }
        }

        // ---- scale + causal mask ----
        const bool needmask = (j0 + 63 > wrow);
#pragma unroll
        for (int nf = 0; nf < 8; nf++) {
#pragma unroll
            for (int e = 0; e < 4; e++) {
                float vsc = sacc[nf][e] * 8.0f;
                if (needmask) {
                    const int col = j0 + nf * 8 + tig * 2 + (e & 1);
                    const int row = (e < 2) ? rA : (rA + 8);
                    if (col > row) vsc = NEG_VAL;
                }
                sacc[nf][e] = vsc;
            }
        }

        // ---- online softmax ----
        float mxA = -CUDART_INF_F, mxB = -CUDART_INF_F;
#pragma unroll
        for (int nf = 0; nf < 8; nf++) {
            mxA = fmaxf(mxA, fmaxf(sacc[nf][0], sacc[nf][1]));
            mxB = fmaxf(mxB, fmaxf(sacc[nf][2], sacc[nf][3]));
        }
        mxA = fmaxf(mxA, __shfl_xor_sync(0xffffffffu, mxA, 1));
        mxA = fmaxf(mxA, __shfl_xor_sync(0xffffffffu, mxA, 2));
        mxB = fmaxf(mxB, __shfl_xor_sync(0xffffffffu, mxB, 1));
        mxB = fmaxf(mxB, __shfl_xor_sync(0xffffffffu, mxB, 2));

        const float mnA = fmaxf(mA, mxA), mnB = fmaxf(mB, mxB);
        const float alA = __expf(mA - mnA), alB = __expf(mB - mnB);

        float psA = 0.f, psB = 0.f;
        uint32_t phiA[8], phiB[8], ploA[8], ploB[8];
#pragma unroll
        for (int nf = 0; nf < 8; nf++) {
            const float p0 = __expf(sacc[nf][0] - mnA);
            const float p1 = __expf(sacc[nf][1] - mnA);
            const float p2 = __expf(sacc[nf][2] - mnB);
            const float p3 = __expf(sacc[nf][3] - mnB);
            psA += p0 + p1; psB += p2 + p3;
            bf16 h0 = __float2bfloat16_rn(p0), h1 = __float2bfloat16_rn(p1);
            bf16 h2 = __float2bfloat16_rn(p2), h3 = __float2bfloat16_rn(p3);
            phiA[nf] = packb(h0, h1);
            phiB[nf] = packb(h2, h3);
            ploA[nf] = packb(__float2bfloat16_rn(p0 - __bfloat162float(h0)),
                             __float2bfloat16_rn(p1 - __bfloat162float(h1)));
            ploB[nf] = packb(__float2bfloat16_rn(p2 - __bfloat162float(h2)),
                             __float2bfloat16_rn(p3 - __bfloat162float(h3)));
        }
        psA += __shfl_xor_sync(0xffffffffu, psA, 1);
        psA += __shfl_xor_sync(0xffffffffu, psA, 2);
        psB += __shfl_xor_sync(0xffffffffu, psB, 1);
        psB += __shfl_xor_sync(0xffffffffu, psB, 2);

        lA = lA * alA + psA; lB = lB * alB + psB;
        mA = mnA; mB = mnB;
#pragma unroll
        for (int nt = 0; nt < 8; nt++) {
            oacc[nt][0] *= alA; oacc[nt][1] *= alA;
            oacc[nt][2] *= alB; oacc[nt][3] *= alB;
        }

        // ---- O += P @ V (V frags via x4.trans covering 16 cols) ----
#pragma unroll
        for (int kc = 0; kc < 4; kc++) {
            uint32_t ah[4] = { phiA[2 * kc], phiB[2 * kc],
                               phiA[2 * kc + 1], phiB[2 * kc + 1] };
            uint32_t al[4] = { ploA[2 * kc], ploB[2 * kc],
                               ploA[2 * kc + 1], ploB[2 * kc + 1] };
#pragma unroll
            for (int ntp = 0; ntp < 4; ntp++) {
                uint32_t vh[4], vl[4];
                const uint32_t ev =
                    (uint32_t)((kc * 16 + (lane & 15)) * 72
                               + ntp * 16 + ((lane >> 4) & 1) * 8) * 2;
                ldm_x4t(vh, smb + (kst + OVHI) * 2 + ev);
                ldm_x4t(vl, smb + (kst + OVLO) * 2 + ev);
#pragma unroll
                for (int hf = 0; hf < 2; hf++) {
                    float* oa = oacc[ntp * 2 + hf];
                    mma_bf16(oa, ah, &vh[hf * 2]);
                    mma_bf16(oa, al, &vh[hf * 2]);
                    mma_bf16(oa, ah, &vl[hf * 2]);
                }
            }
        }
        __syncthreads();
    }

    // ---- epilogue: O/l, split to bf16 hi/lo ----
    const float ivA = 1.f / lA, ivB = 1.f / lB;
    const size_t gra = (size_t)b * SEQ + rA;
#pragma unroll
    for (int nt = 0; nt < 8; nt++) {
        const int col = h * 64 + nt * 8 + tig * 2;
        const float v0 = oacc[nt][0] * ivA, v1 = oacc[nt][1] * ivA;
        const float v2 = oacc[nt][2] * ivB, v3 = oacc[nt][3] * ivB;
        bf16 h0 = __float2bfloat16_rn(v0), h1 = __float2bfloat16_rn(v1);
        bf16 h2 = __float2bfloat16_rn(v2), h3 = __float2bfloat16_rn(v3);
        const size_t iA = (gra * DMODEL + col) >> 1;
        const size_t iB = ((gra + 8) * DMODEL + col) >> 1;
        ((uint32_t*)ohi)[iA] = packb(h0, h1);
        ((uint32_t*)olo)[iA] = packb(__float2bfloat16_rn(v0 - __bfloat162float(h0)),
                                     __float2bfloat16_rn(v1 - __bfloat162float(h1)));
        ((uint32_t*)ohi)[iB] = packb(h2, h3);
        ((uint32_t*)olo)[iB] = packb(__float2bfloat16_rn(v2 - __bfloat162float(h2)),
                                     __float2bfloat16_rn(v3 - __bfloat162float(h3)));
    }
}

// ===========================================================================
extern "C" void kernel_launch(void* const* d_in, const int* in_sizes, int n_in,
                              void* d_out, int out_size)
{
    const float* q     = (const float*)d_in[0];
    const float* k     = (const float*)d_in[1];
    const float* v     = (const float*)d_in[2];
    const float* w_qkv = (const float*)d_in[3];
    const float* b_qkv = (const float*)d_in[4];
    const float* w_out = (const float*)d_in[5];
    const float* b_out = (const float*)d_in[6];
    float* out = (float*)d_out;

    bf16 *in_hi, *in_lo, *wqkv_hi, *wqkv_lo, *qkv_hi, *qkv_lo;
    bf16 *attn_hi, *attn_lo, *wout_hi, *wout_lo;
    cudaGetSymbolAddress((void**)&in_hi,   g_in_hi);
    cudaGetSymbolAddress((void**)&in_lo,   g_in_lo);
    cudaGetSymbolAddress((void**)&wqkv_hi, g_wqkv_hi);
    cudaGetSymbolAddress((void**)&wqkv_lo, g_wqkv_lo);
    cudaGetSymbolAddress((void**)&qkv_hi,  g_qkv_hi);
    cudaGetSymbolAddress((void**)&qkv_lo,  g_qkv_lo);
    cudaGetSymbolAddress((void**)&attn_hi, g_attn_hi);
    cudaGetSymbolAddress((void**)&attn_lo, g_attn_lo);
    cudaGetSymbolAddress((void**)&wout_hi, g_wout_hi);
    cudaGetSymbolAddress((void**)&wout_lo, g_wout_lo);

    cudaFuncSetAttribute(gemm_bf16<0>,
                         cudaFuncAttributeMaxDynamicSharedMemorySize, GEMM_SMEM);
    cudaFuncSetAttribute(gemm_bf16<1>,
                         cudaFuncAttributeMaxDynamicSharedMemorySize, GEMM_SMEM);
    cudaFuncSetAttribute(attn_mma,
                         cudaFuncAttributeMaxDynamicSharedMemorySize, ATTN_SMEM);

    // 0) splits
    split_concat<<<(MTOT * K3 / 4) / 256, 256>>>(q, k, v, in_hi, in_lo);
    split_plain<<<(K3 * K3 / 4) / 256, 256>>>(w_qkv, wqkv_hi, wqkv_lo);
    split_plain<<<(DMODEL * DMODEL / 4) / 256, 256>>>(w_out, wout_hi, wout_lo);

    // 1) QKV projection -> bf16 hi/lo qkv
    {
        dim3 g(K3 / 128, MTOT / 128);
        gemm_bf16<1><<<g, 256, GEMM_SMEM>>>(in_hi, in_lo, wqkv_hi, wqkv_lo,
                                            b_qkv, nullptr, qkv_hi, qkv_lo,
                                            MTOT, K3, K3);
    }

    // 2) attention -> bf16 hi/lo attn
    {
        dim3 g(SEQ / 128, NHEADS, BATCH);
        attn_mma<<<g, 256, ATTN_SMEM>>>(qkv_hi, qkv_lo, attn_hi, attn_lo);
    }

    // 3) output projection -> fp32 out
    {
        dim3 g(DMODEL / 128, MTOT / 128);
        gemm_bf16<0><<<g, 256, GEMM_SMEM>>>(attn_hi, attn_lo, wout_hi, wout_lo,
                                            b_out, out, nullptr, nullptr,
                                            MTOT, DMODEL, DMODEL);
    }
}